// round 16
// baseline (speedup 1.0000x reference)
#include <cuda_runtime.h>
#include <cuda_bf16.h>
#include <cstdint>

// UniformNeighborSampler, rank selection with 32-bit keys.
//
// Per row: gather 128 neighbor ids + their probs, emit top-25 ids (desc prob,
// ties -> lower index) as float32.
//
// 2 warps per row, 2 elements per lane (256-thread block = 4 rows) for high
// occupancy / gather-latency hiding. Keys are the raw float bits of w
// (w in [0,1) => positive => bit order == value order). rank = #{j: k_j > k}.
// Duplicate values share a rank; detected via atomicMin(owner[rank], elem);
// non-owning elements run a rare scalar fixup rank += #{j < e: k_j == k},
// exactly reproducing jax.lax.top_k's stable tie-break.

#define N_NODES     20000
#define MAX_DEGREE  128
#define BATCH       4096
#define NUM_SAMPLES 25
#define ROWS_PER_BLOCK 4
#define THREADS     256   // 8 warps: warp w -> row w>>1, half w&1

__global__ __launch_bounds__(THREADS)
void uns_rank32_split_kernel(const int* __restrict__ ids,
                             const int* __restrict__ adj_info,
                             const float* __restrict__ prob,
                             float* __restrict__ out)
{
    __shared__ unsigned int skey[ROWS_PER_BLOCK][MAX_DEGREE];
    __shared__ int          sown[ROWS_PER_BLOCK][MAX_DEGREE];

    const int warp = threadIdx.x >> 5;
    const int lane = threadIdx.x & 31;
    const int r    = warp >> 1;            // row within block
    const int half = warp & 1;             // which 64-element half of the row
    const int row  = blockIdx.x * ROWS_PER_BLOCK + r;

    const int id = __ldg(&ids[row]);

    // coalesced: lane loads 2 consecutive neighbor ids from its half
    const int2 nb = reinterpret_cast<const int2*>(
                        adj_info + (long long)id * MAX_DEGREE + half * 64)[lane];

    const float* prow = prob + (long long)id * N_NODES;

    // 2 independent random gathers per lane
    const float w0 = __ldg(&prow[nb.x]);
    const float w1 = __ldg(&prow[nb.y]);

    // w in [0,1) -> positive float: raw bits are order-preserving
    const unsigned int k0 = __float_as_uint(w0);
    const unsigned int k1 = __float_as_uint(w1);

    const int e = half * 64 + lane * 2;    // element index within row

    reinterpret_cast<uint2*>(skey[r])[e >> 1] = make_uint2(k0, k1);
    reinterpret_cast<int2*>(sown[r])[e >> 1]  = make_int2(0x7FFFFFFF, 0x7FFFFFFF);
    __syncthreads();

    // rank = count of strictly-greater keys; 8 independent cmp+add per chunk
    int r0 = 0, r1 = 0;
    #pragma unroll 8
    for (int j = 0; j < MAX_DEGREE / 4; j++) {
        const uint4 kk = reinterpret_cast<const uint4*>(skey[r])[j];  // broadcast
        r0 += (kk.x > k0); r0 += (kk.y > k0); r0 += (kk.z > k0); r0 += (kk.w > k0);
        r1 += (kk.x > k1); r1 += (kk.y > k1); r1 += (kk.z > k1); r1 += (kk.w > k1);
    }

    atomicMin(&sown[r][r0], e + 0);
    atomicMin(&sown[r][r1], e + 1);
    __syncthreads();

    float* orow = out + (long long)row * NUM_SAMPLES;

    // Per element: if I don't own my rank slot, I'm a non-minimal twin ->
    // exact stable fixup (rare: ~1-2 elements in ~half the rows).
    #pragma unroll
    for (int m = 0; m < 2; m++) {
        int            rm = (m == 0) ? r0 : r1;
        const unsigned km = (m == 0) ? k0 : k1;
        const int     nbm = (m == 0) ? nb.x : nb.y;
        const int      em = e + m;

        if (sown[r][rm] != em) {
            int eq = 0;
            for (int j = 0; j < em; j++) eq += (skey[r][j] == km);
            rm += eq;
        }
        if (rm < NUM_SAMPLES) {
            orow[rm] = (float)nbm;   // ids < 2^24: exact in float32
        }
    }
}

extern "C" void kernel_launch(void* const* d_in, const int* in_sizes, int n_in,
                              void* d_out, int out_size)
{
    // Identify inputs by size (robust to metadata ordering). Element counts:
    //   ids: 4096, adj_info: 2,560,000, prob_matrix: 400,000,000
    const int*   ids  = nullptr;
    const int*   adj  = nullptr;
    const float* prob = nullptr;

    const long long S_IDS  = (long long)BATCH;
    const long long S_ADJ  = (long long)N_NODES * MAX_DEGREE;
    const long long S_PROB = (long long)N_NODES * N_NODES;

    for (int i = 0; i < n_in; i++) {
        long long sz = (long long)(unsigned int)in_sizes[i];
        if (sz == S_IDS  || sz == S_IDS  * 4) ids  = (const int*)d_in[i];
        else if (sz == S_ADJ  || sz == S_ADJ  * 4) adj  = (const int*)d_in[i];
        else if (sz == S_PROB || sz == S_PROB * 4) prob = (const float*)d_in[i];
    }
    if (!ids || !adj || !prob) {  // fallback: setup_inputs dict order
        ids  = (const int*)d_in[0];
        adj  = (const int*)d_in[1];
        prob = (const float*)d_in[2];
    }

    float* out = (float*)d_out;

    uns_rank32_split_kernel<<<BATCH / ROWS_PER_BLOCK, THREADS>>>(ids, adj, prob, out);
}

// round 17
// speedup vs baseline: 1.0890x; 1.0890x over previous
#include <cuda_runtime.h>
#include <cuda_bf16.h>
#include <cstdint>

// UniformNeighborSampler, warp-per-row rank selection, dual-pipe compare loop.
//
// Per row: gather 128 neighbor ids + their probs, emit top-25 ids (desc prob,
// ties -> lower index) as float32.
//
// One warp per row, 4 elements per lane. w in [0,1) -> positive floats: raw
// bit order == value order, so elements 0-1 are ranked with FLOAT compares
// (fma pipe) and elements 2-3 with INT compares (alu pipe) -- both pipes have
// rt_SMSP=2, so interleaving doubles the issue throughput of the O(n^2)
// compare loop vs the pure-ALU version.
//
// rank = #{j: k_j > k}. Duplicate values share a rank; detected via
// atomicMin(owner[rank], elem); non-owning elements run a rare scalar fixup
// rank += #{j < e: k_j == k}, exactly reproducing jax.lax.top_k's stable
// tie-break.

#define N_NODES     20000
#define MAX_DEGREE  128
#define BATCH       4096
#define NUM_SAMPLES 25
#define ROWS_PER_BLOCK 4
#define THREADS     (ROWS_PER_BLOCK * 32)

__global__ __launch_bounds__(THREADS)
void uns_rank_dualpipe_kernel(const int* __restrict__ ids,
                              const int* __restrict__ adj_info,
                              const float* __restrict__ prob,
                              float* __restrict__ out)
{
    __shared__ unsigned int skey[ROWS_PER_BLOCK][MAX_DEGREE];
    __shared__ int          sown[ROWS_PER_BLOCK][MAX_DEGREE];

    const int warp = threadIdx.x >> 5;
    const int lane = threadIdx.x & 31;
    const int row  = blockIdx.x * ROWS_PER_BLOCK + warp;

    const int id = __ldg(&ids[row]);

    // coalesced: lane loads 4 consecutive neighbor ids (512B-aligned row)
    const int4 nb = reinterpret_cast<const int4*>(
                        adj_info + (long long)id * MAX_DEGREE)[lane];

    const float* prow = prob + (long long)id * N_NODES;

    // 4 independent random gathers per lane (MLP=4)
    const float w0 = __ldg(&prow[nb.x]);
    const float w1 = __ldg(&prow[nb.y]);
    const float w2 = __ldg(&prow[nb.z]);
    const float w3 = __ldg(&prow[nb.w]);

    const unsigned int k0 = __float_as_uint(w0);
    const unsigned int k1 = __float_as_uint(w1);
    const unsigned int k2 = __float_as_uint(w2);
    const unsigned int k3 = __float_as_uint(w3);

    reinterpret_cast<uint4*>(skey[warp])[lane] = make_uint4(k0, k1, k2, k3);
    reinterpret_cast<int4*>(sown[warp])[lane]  = make_int4(0x7FFFFFFF, 0x7FFFFFFF,
                                                           0x7FFFFFFF, 0x7FFFFFFF);
    __syncwarp();

    // Dual-pipe rank loop: elems 0-1 in float (fma pipe), elems 2-3 in int (alu).
    float fr0 = 0.0f, fr1 = 0.0f;
    int   r2 = 0,     r3 = 0;
    #pragma unroll 8
    for (int j = 0; j < MAX_DEGREE / 4; j++) {
        const uint4 kk = reinterpret_cast<const uint4*>(skey[warp])[j];  // broadcast
        const float ax = __uint_as_float(kk.x);
        const float ay = __uint_as_float(kk.y);
        const float az = __uint_as_float(kk.z);
        const float aw = __uint_as_float(kk.w);

        if (ax > w0) fr0 += 1.0f;
        if (ay > w0) fr0 += 1.0f;
        if (az > w0) fr0 += 1.0f;
        if (aw > w0) fr0 += 1.0f;

        if (ax > w1) fr1 += 1.0f;
        if (ay > w1) fr1 += 1.0f;
        if (az > w1) fr1 += 1.0f;
        if (aw > w1) fr1 += 1.0f;

        r2 += (kk.x > k2); r2 += (kk.y > k2); r2 += (kk.z > k2); r2 += (kk.w > k2);
        r3 += (kk.x > k3); r3 += (kk.y > k3); r3 += (kk.z > k3); r3 += (kk.w > k3);
    }
    int r0 = (int)fr0;   // exact: small integer counts
    int r1 = (int)fr1;

    const int e = lane * 4;
    atomicMin(&sown[warp][r0], e + 0);
    atomicMin(&sown[warp][r1], e + 1);
    atomicMin(&sown[warp][r2], e + 2);
    atomicMin(&sown[warp][r3], e + 3);
    __syncwarp();

    float* orow = out + (long long)row * NUM_SAMPLES;

    // Per element: if I don't own my rank slot, I'm a non-minimal twin ->
    // exact stable fixup (rare: ~1-2 elements in ~half the rows).
    #pragma unroll
    for (int m = 0; m < 4; m++) {
        int           rm = (m == 0) ? r0 : (m == 1) ? r1 : (m == 2) ? r2 : r3;
        const unsigned km = (m == 0) ? k0 : (m == 1) ? k1 : (m == 2) ? k2 : k3;
        const int     nbm = (m == 0) ? nb.x : (m == 1) ? nb.y : (m == 2) ? nb.z : nb.w;
        const int      em = e + m;

        if (sown[warp][rm] != em) {
            int eq = 0;
            for (int j = 0; j < em; j++) eq += (skey[warp][j] == km);
            rm += eq;
        }
        if (rm < NUM_SAMPLES) {
            orow[rm] = (float)nbm;   // ids < 2^24: exact in float32
        }
    }
}

extern "C" void kernel_launch(void* const* d_in, const int* in_sizes, int n_in,
                              void* d_out, int out_size)
{
    // Identify inputs by size (robust to metadata ordering). Element counts:
    //   ids: 4096, adj_info: 2,560,000, prob_matrix: 400,000,000
    const int*   ids  = nullptr;
    const int*   adj  = nullptr;
    const float* prob = nullptr;

    const long long S_IDS  = (long long)BATCH;
    const long long S_ADJ  = (long long)N_NODES * MAX_DEGREE;
    const long long S_PROB = (long long)N_NODES * N_NODES;

    for (int i = 0; i < n_in; i++) {
        long long sz = (long long)(unsigned int)in_sizes[i];
        if (sz == S_IDS  || sz == S_IDS  * 4) ids  = (const int*)d_in[i];
        else if (sz == S_ADJ  || sz == S_ADJ  * 4) adj  = (const int*)d_in[i];
        else if (sz == S_PROB || sz == S_PROB * 4) prob = (const float*)d_in[i];
    }
    if (!ids || !adj || !prob) {  // fallback: setup_inputs dict order
        ids  = (const int*)d_in[0];
        adj  = (const int*)d_in[1];
        prob = (const float*)d_in[2];
    }

    float* out = (float*)d_out;

    uns_rank_dualpipe_kernel<<<BATCH / ROWS_PER_BLOCK, THREADS>>>(ids, adj, prob, out);
}